// round 7
// baseline (speedup 1.0000x reference)
#include <cuda_runtime.h>
#include <cuda_bf16.h>
#include <cstdint>
#include <cstddef>

#define D_TOTAL   786432
#define TILE      64                 // d's per chunk (64 bf16 = 128B = SW128 row)
#define N_TILES   (D_TOTAL / TILE)   // 12288
#define BATCH     64
#define NBLK      296
#define NTHREADS  256
#define NJ        25                 // 24 dots + sumsq

// smem byte offsets within 128B-aligned region
#define A_OFF(b)   ((b) * 16384)            // A: 128 rows x 128B
#define BH_OFF(b)  (32768 + (b) * 6144)     // Bh: 24 rows x 128B
#define BL_OFF(b)  (BH_OFF(b) + 3072)       // Bl: 24 rows x 128B
#define SMEM_BYTES 45056

__device__ float    g_partial[BATCH * NJ * NBLK];   // [b][j][blk]
__device__ unsigned g_count;                         // zero-init; reset each run

typedef unsigned int u32;

__device__ __forceinline__ u32 smem_u32(const void* p) {
    return (u32)__cvta_generic_to_shared(p);
}
__device__ __forceinline__ u32 swz(u32 x) { return x ^ ((x >> 3) & 0x70); }

#define STS2(a, x, y) asm volatile("st.shared.v2.b32 [%0], {%1,%2};" :: "r"(a), "r"(x), "r"(y) : "memory")
#define LDSM4(r0,r1,r2,r3,a) asm volatile( \
    "ldmatrix.sync.aligned.m8n8.x4.shared.b16 {%0,%1,%2,%3}, [%4];" \
    : "=r"(r0), "=r"(r1), "=r"(r2), "=r"(r3) : "r"(a))
#define LDSM2(r0,r1,a) asm volatile( \
    "ldmatrix.sync.aligned.m8n8.x2.shared.b16 {%0,%1}, [%2];" \
    : "=r"(r0), "=r"(r1) : "r"(a))
#define MMA16816(c, a0,a1,a2,a3, b0,b1) asm volatile( \
    "mma.sync.aligned.m16n8k16.row.col.f32.bf16.bf16.f32 " \
    "{%0,%1,%2,%3}, {%4,%5,%6,%7}, {%8,%9}, {%0,%1,%2,%3};" \
    : "+f"((c)[0]), "+f"((c)[1]), "+f"((c)[2]), "+f"((c)[3]) \
    : "r"(a0), "r"(a1), "r"(a2), "r"(a3), "r"(b0), "r"(b1))

__device__ __forceinline__ u32 packbf(float lo, float hi) {
    u32 r;
    asm("cvt.rn.bf16x2.f32 %0, %1, %2;" : "=r"(r) : "f"(hi), "f"(lo));
    return r;
}
// 4 fp32 -> hi bf16x2 pair + residual-lo bf16x2 pair
__device__ __forceinline__ void split4(float a0, float a1, float a2, float a3,
                                       u32& h0, u32& h1, u32& l0, u32& l1) {
    h0 = packbf(a0, a1);
    h1 = packbf(a2, a3);
    float e0 = a0 - __uint_as_float(h0 << 16);
    float e1 = a1 - __uint_as_float(h0 & 0xffff0000u);
    float e2 = a2 - __uint_as_float(h1 << 16);
    float e3 = a3 - __uint_as_float(h1 & 0xffff0000u);
    l0 = packbf(e0, e1);
    l1 = packbf(e2, e3);
}

__global__ void __launch_bounds__(NTHREADS, 2)
mhc_fused_v2(const float* __restrict__ x, const float* __restrict__ wn,
             const float* __restrict__ Wpre, const float* __restrict__ Wpost,
             const float* __restrict__ Wres,
             const float* __restrict__ b_pre, const float* __restrict__ b_post,
             const float* __restrict__ b_res, const float* __restrict__ a_pre,
             const float* __restrict__ a_post, const float* __restrict__ a_res,
             float* __restrict__ out)
{
    __shared__ __align__(128) char sm[SMEM_BYTES];
    __shared__ unsigned s_done;

    const u32 sbase = smem_u32(sm);
    const int t    = threadIdx.x;
    const int lane = t & 31;
    const int w    = t >> 5;
    const int r    = t >> 2;            // x row 0..63
    const int seg  = (t & 3) << 4;      // 16-float segment within 64-d chunk

    // per-thread ldmatrix source offsets (bytes, pre-swizzle)
    const u32 a_off0 = (u32)(((w << 4) + (lane & 15)) << 7) + (u32)((lane >> 4) << 4);
    const u32 b_off0 = (u32)((lane & 7) << 7) + (u32)(((lane >> 3) & 1) << 4);

    const float* xrow = x + (size_t)r * D_TOTAL + seg;
    const float* wrow = 0;
    if (t < 96) {
        int rw = t >> 2;
        wrow = (rw < 4) ? (Wpre  + (size_t)rw * D_TOTAL)
             : (rw < 8) ? (Wpost + (size_t)(rw - 4) * D_TOTAL)
                        : (Wres  + (size_t)(rw - 8) * D_TOTAL);
        wrow += seg;
    }

    float accH[3][4], accL[3][4];
#pragma unroll
    for (int n = 0; n < 3; n++)
#pragma unroll
        for (int c = 0; c < 4; c++) { accH[n][c] = 0.f; accL[n][c] = 0.f; }
    float ssq = 0.f;

    float4 xv[4], gv[4], wv[4];
    // initial prefetch
    {
        const int d0 = blockIdx.x * TILE;
        const float4* xp = (const float4*)(xrow + d0);
        const float4* gp = (const float4*)(wn + d0 + seg);
#pragma unroll
        for (int q = 0; q < 4; q++) { xv[q] = xp[q]; gv[q] = gp[q]; }
        if (t < 96) {
            const float4* vp = (const float4*)(wrow + d0);
#pragma unroll
            for (int q = 0; q < 4; q++) wv[q] = vp[q];
        }
    }

    int it = 0;
    for (int tile = blockIdx.x; tile < N_TILES; tile += NBLK, ++it) {
        const int bu = it & 1;
        __syncthreads();   // buffer bu free (reads from iter it-2 done)

        // ---- convert x from regs: sumsq, fold w_norm, hi/lo split, swizzled STS
        {
            const u32 abase = sbase + A_OFF(bu);
#pragma unroll
            for (int q = 0; q < 4; q++) {
                float4 v = xv[q], g = gv[q];
                ssq = fmaf(v.x, v.x, ssq); ssq = fmaf(v.y, v.y, ssq);
                ssq = fmaf(v.z, v.z, ssq); ssq = fmaf(v.w, v.w, ssq);
                u32 h0, h1, l0, l1;
                split4(v.x * g.x, v.y * g.y, v.z * g.z, v.w * g.w, h0, h1, l0, l1);
                u32 off = (u32)((r << 7) + (seg << 1) + (q << 3));
                STS2(abase + swz(off), h0, h1);
                STS2(abase + swz(off + (64 << 7)), l0, l1);
            }
        }
        if (t < 96) {
            const u32 hb = sbase + BH_OFF(bu);
            const u32 lb = sbase + BL_OFF(bu);
            int rw = t >> 2;
#pragma unroll
            for (int q = 0; q < 4; q++) {
                float4 v = wv[q];
                u32 h0, h1, l0, l1;
                split4(v.x, v.y, v.z, v.w, h0, h1, l0, l1);
                u32 off = (u32)((rw << 7) + (seg << 1) + (q << 3));
                STS2(hb + swz(off), h0, h1);
                STS2(lb + swz(off), l0, l1);
            }
        }
        __syncthreads();   // staged data visible

        // ---- prefetch next chunk into regs (hidden behind MMA phase)
        {
            const int nt = tile + NBLK;
            if (nt < N_TILES) {
                const int d0 = nt * TILE;
                const float4* xp = (const float4*)(xrow + d0);
                const float4* gp = (const float4*)(wn + d0 + seg);
#pragma unroll
                for (int q = 0; q < 4; q++) { xv[q] = xp[q]; gv[q] = gp[q]; }
                if (t < 96) {
                    const float4* vp = (const float4*)(wrow + d0);
#pragma unroll
                    for (int q = 0; q < 4; q++) wv[q] = vp[q];
                }
            }
        }

        // ---- MMA phase: warp w covers A rows w*16..+15
        {
            const u32 Ab = sbase + A_OFF(bu);
            const u32 Bh = sbase + BH_OFF(bu);
            const u32 Bl = sbase + BL_OFF(bu);
#pragma unroll
            for (int k = 0; k < 4; k++) {
                u32 a0, a1, a2, a3;
                LDSM4(a0, a1, a2, a3, Ab + swz(a_off0 + k * 32));
#pragma unroll
                for (int n = 0; n < 3; n++) {
                    u32 bo = b_off0 + (u32)(n << 10) + (u32)(k * 32);
                    u32 b0, b1;
                    LDSM2(b0, b1, Bh + swz(bo));
                    MMA16816(accH[n], a0, a1, a2, a3, b0, b1);
                    if (w < 4) {
                        u32 c0, c1;
                        LDSM2(c0, c1, Bl + swz(bo));
                        MMA16816(accL[n], a0, a1, a2, a3, c0, c1);
                    }
                }
            }
        }
    }

    // ================= epilogue: per-block partials =================
    __syncthreads();
    float* crossA = (float*)sm;              // [128][25]
    float* cross2 = crossA + 128 * 25;       // [64][25]
    float* ssqred = cross2 + 64 * 25;        // [256]
    ssqred[t] = ssq;
    {
        int row0 = (w << 4) + (lane >> 2);
        int col0 = (lane & 3) << 1;
#pragma unroll
        for (int n = 0; n < 3; n++) {
            int c = n * 8 + col0;
            crossA[row0 * 25 + c]           = accH[n][0];
            crossA[row0 * 25 + c + 1]       = accH[n][1];
            crossA[(row0 + 8) * 25 + c]     = accH[n][2];
            crossA[(row0 + 8) * 25 + c + 1] = accH[n][3];
            if (w < 4) {
                cross2[row0 * 25 + c]           = accL[n][0];
                cross2[row0 * 25 + c + 1]       = accL[n][1];
                cross2[(row0 + 8) * 25 + c]     = accL[n][2];
                cross2[(row0 + 8) * 25 + c + 1] = accL[n][3];
            }
        }
    }
    __syncthreads();

    if (t < 64) {
        float* dst = g_partial + (size_t)t * NJ * NBLK + blockIdx.x;
#pragma unroll
        for (int j = 0; j < 24; j++) {
            float val = crossA[t * 25 + j] + crossA[(64 + t) * 25 + j] + cross2[t * 25 + j];
            dst[(size_t)j * NBLK] = val;
        }
        float s = ssqred[4 * t] + ssqred[4 * t + 1] + ssqred[4 * t + 2] + ssqred[4 * t + 3];
        dst[(size_t)24 * NBLK] = s;
    }

    // ================= fused finalize: last block reduces =================
    __threadfence();
    if (t == 0) s_done = (atomicAdd(&g_count, 1) == NBLK - 1) ? 1u : 0u;
    __syncthreads();
    if (!s_done) return;
    __threadfence();

    float* vsm = (float*)sm;                 // [64][25]
    __syncthreads();
    for (int task = t; task < BATCH * NJ; task += NTHREADS) {
        int b = task / NJ, j = task % NJ;
        const float4* src = (const float4*)(g_partial + ((size_t)b * NJ + j) * NBLK);
        float4 a = make_float4(0.f, 0.f, 0.f, 0.f);
#pragma unroll 8
        for (int m = 0; m < NBLK / 4; m++) {
            float4 u = src[m];
            a.x += u.x; a.y += u.y; a.z += u.z; a.w += u.w;
        }
        vsm[b * NJ + j] = (a.x + a.y) + (a.z + a.w);
    }
    __syncthreads();

    {
        const int sub = lane & 15;
        const float ap = a_pre[0], ao = a_post[0], ar = a_res[0];
#pragma unroll
        for (int q = 0; q < 4; q++) {
            int b = (w << 3) + (q << 1) + (lane >> 4);
            const float* v = vsm + b * NJ;
            // ms = mean(x^2); eps = FLT_EPSILON (torch RMSNorm eps=None semantics)
            float rinv = rsqrtf(v[24] * (1.0f / (float)D_TOTAL) + 1.1920929e-7f);
            if (sub < 4) {
                float p = ap * (v[sub] * rinv) + b_pre[sub];
                out[b * 4 + sub] = 1.f / (1.f + __expf(-p));
                float qq = ao * (v[4 + sub] * rinv) + b_post[sub];
                out[256 + b * 4 + sub] = 2.f / (1.f + __expf(-qq));
            }
            // Sinkhorn on 4x4: sub = i*4 + j (xor<=8 stays within 16-lane half)
            float rr = ar * (v[8 + sub] * rinv) + b_res[sub];
            float m = rr;
            m = fmaxf(m, __shfl_xor_sync(0xffffffffu, m, 1));
            m = fmaxf(m, __shfl_xor_sync(0xffffffffu, m, 2));
            float M = __expf(rr - m);
#pragma unroll
            for (int itr = 0; itr < 20; itr++) {
                float rs = M + __shfl_xor_sync(0xffffffffu, M, 1);
                rs += __shfl_xor_sync(0xffffffffu, rs, 2);
                M = __fdividef(M, rs + 1e-6f);
                float cs = M + __shfl_xor_sync(0xffffffffu, M, 4);
                cs += __shfl_xor_sync(0xffffffffu, cs, 8);
                M = __fdividef(M, cs + 1e-6f);
            }
            out[512 + b * 16 + sub] = M;
        }
    }
    if (t == 0) g_count = 0;   // reset for next replay
}

extern "C" void kernel_launch(void* const* d_in, const int* in_sizes, int n_in,
                              void* d_out, int out_size)
{
    const float* x     = (const float*)d_in[0];
    const float* wnorm = (const float*)d_in[1];
    const float* Wpre  = (const float*)d_in[2];
    const float* Wpost = (const float*)d_in[3];
    const float* Wres  = (const float*)d_in[4];
    const float* bpre  = (const float*)d_in[5];
    const float* bpost = (const float*)d_in[6];
    const float* bres  = (const float*)d_in[7];
    const float* apre  = (const float*)d_in[8];
    const float* apost = (const float*)d_in[9];
    const float* ares  = (const float*)d_in[10];
    float* out = (float*)d_out;

    mhc_fused_v2<<<NBLK, NTHREADS>>>(x, wnorm, Wpre, Wpost, Wres,
                                     bpre, bpost, bres, apre, apost, ares, out);
}

// round 9
// speedup vs baseline: 1.3849x; 1.3849x over previous
#include <cuda_runtime.h>
#include <cstdint>
#include <cstddef>

#define D_TOTAL   786432
#define TILE      64
#define N_TILES   (D_TOTAL / TILE)   // 12288
#define BATCH     64
#define NBLK      296
#define NTHREADS  256
#define NJ        25                 // 24 dots + sumsq

#define XP        68                 // x smem pitch (floats): banks (4g+c) conflict-free
#define WP        68                 // W smem pitch
#define X_OFF     0
#define W_OFF     (64 * XP)          // 4352
#define WN_OFF    (W_OFF + 24 * WP)  // 5984
#define BUFF      (WN_OFF + 64)      // 6048 floats -> 2 buffers = 48384 B static

__device__ float    g_partial[BATCH * NJ * NBLK];   // [b][j][blk]
__device__ unsigned g_count;                        // zero-init; reset each run

typedef unsigned int u32;

__device__ __forceinline__ u32 smem_u32(const void* p) {
    return (u32)__cvta_generic_to_shared(p);
}
#define CPA16(d, s)  asm volatile("cp.async.ca.shared.global [%0], [%1], 16;" :: "r"(d), "l"(s))
#define CPCOMMIT()   asm volatile("cp.async.commit_group;")
#define CPWAIT1()    asm volatile("cp.async.wait_group 1;")
#define CPWAIT0()    asm volatile("cp.async.wait_group 0;")

__device__ __forceinline__ u32 cvt_tf32(float v) {
    u32 r;
    asm("cvt.rna.tf32.f32 %0, %1;" : "=r"(r) : "f"(v));
    return r;
}
#define MMA_TF32(c, a0,a1,a2,a3, b0,b1) asm volatile( \
    "mma.sync.aligned.m16n8k8.row.col.f32.tf32.tf32.f32 " \
    "{%0,%1,%2,%3}, {%4,%5,%6,%7}, {%8,%9}, {%0,%1,%2,%3};" \
    : "+f"((c)[0]), "+f"((c)[1]), "+f"((c)[2]), "+f"((c)[3]) \
    : "r"(a0), "r"(a1), "r"(a2), "r"(a3), "r"(b0), "r"(b1))

__global__ void __launch_bounds__(NTHREADS, 2)
mhc_tf32_r9(const float* __restrict__ x, const float* __restrict__ wn,
            const float* __restrict__ Wpre, const float* __restrict__ Wpost,
            const float* __restrict__ Wres,
            const float* __restrict__ b_pre, const float* __restrict__ b_post,
            const float* __restrict__ b_res, const float* __restrict__ a_pre,
            const float* __restrict__ a_post, const float* __restrict__ a_res,
            float* __restrict__ out)
{
    __shared__ __align__(16) float sb[2][BUFF];   // 48384 B
    __shared__ unsigned s_done;

    const int t    = threadIdx.x;
    const int lane = t & 31;
    const int w    = t >> 5;
    const int g    = lane >> 2;     // fragment group row
    const int c    = lane & 3;      // fragment group col
    const int m0   = (w >> 1) << 4; // warp's m-tile base row
    const int k0   = (w & 1) << 5;  // warp's k-split base col

    // stage one 64-d chunk of x/W/wn (raw fp32) into buffer bs via cp.async
    auto stage = [&](int bs, int tile) {
        float* s = sb[bs];
        const int d0 = tile * TILE;
#pragma unroll
        for (int i = 0; i < 4; i++) {                       // x: 64 rows x 4 chunks
            int idx = i * NTHREADS + t;
            int row = idx >> 4, ch = (idx & 15) << 2;
            CPA16(smem_u32(s + row * XP + ch),
                  x + (size_t)row * D_TOTAL + d0 + ch);
        }
#pragma unroll
        for (int i = 0; i < 2; i++) {                       // W: 24 rows x 16 chunks
            int id = i * NTHREADS + t;
            if (id < 384) {
                int row = id >> 4, ch = (id & 15) << 2;
                const float* r = (row < 4) ? (Wpre  + (size_t)row * D_TOTAL)
                               : (row < 8) ? (Wpost + (size_t)(row - 4) * D_TOTAL)
                                           : (Wres  + (size_t)(row - 8) * D_TOTAL);
                CPA16(smem_u32(s + W_OFF + row * WP + ch), r + d0 + ch);
            }
        }
        if (t < 16) CPA16(smem_u32(s + WN_OFF + t * 4), wn + d0 + t * 4);
    };

    float acc[3][4];
#pragma unroll
    for (int n = 0; n < 3; n++)
#pragma unroll
        for (int q = 0; q < 4; q++) acc[n][q] = 0.f;
    float ssqA = 0.f, ssqB = 0.f;

    int buf = 0;
    stage(0, blockIdx.x);
    CPCOMMIT();

    for (int tile = blockIdx.x; tile < N_TILES; tile += NBLK) {
        int nt = tile + NBLK;
        if (nt < N_TILES) { stage(buf ^ 1, nt); CPCOMMIT(); CPWAIT1(); }
        else              { CPWAIT0(); }
        __syncthreads();

        const float* xb  = sb[buf];
        const float* wsb = xb + W_OFF + k0;
        const float* wnb = xb + WN_OFF + k0;
        const float* xr0 = xb + (m0 + g) * XP + k0 + c;
        const float* xr1 = xr0 + 8 * XP;
#pragma unroll
        for (int k = 0; k < 4; k++) {
            const int kk = k * 8;
            float a0 = xr0[kk], a2 = xr0[kk + 4];
            float a1 = xr1[kk], a3 = xr1[kk + 4];
            ssqA = fmaf(a0, a0, ssqA); ssqA = fmaf(a2, a2, ssqA);
            ssqB = fmaf(a1, a1, ssqB); ssqB = fmaf(a3, a3, ssqB);
            u32 ta0 = cvt_tf32(a0), ta1 = cvt_tf32(a1);
            u32 ta2 = cvt_tf32(a2), ta3 = cvt_tf32(a3);
            float wv0 = wnb[kk + c], wv1 = wnb[kk + c + 4];
#pragma unroll
            for (int n = 0; n < 3; n++) {
                const float* br = wsb + (n * 8 + g) * WP + kk + c;
                u32 tb0 = cvt_tf32(br[0] * wv0);
                u32 tb1 = cvt_tf32(br[4] * wv1);
                MMA_TF32(acc[n], ta0, ta1, ta2, ta3, tb0, tb1);
            }
        }
        __syncthreads();
        buf ^= 1;
    }

    // ===== epilogue: k-split combine + per-row sumsq + per-block partials =====
    float* cross = &sb[0][0];                 // [2][64][26]
    float* ssqm  = cross + 2 * 64 * 26;       // [64][8]
    {
        const int ks = w & 1;
        const int row0 = m0 + g, row1 = m0 + g + 8;
#pragma unroll
        for (int n = 0; n < 3; n++) {
            int col = n * 8 + 2 * c;
            cross[(ks * 64 + row0) * 26 + col]     = acc[n][0];
            cross[(ks * 64 + row0) * 26 + col + 1] = acc[n][1];
            cross[(ks * 64 + row1) * 26 + col]     = acc[n][2];
            cross[(ks * 64 + row1) * 26 + col + 1] = acc[n][3];
        }
        ssqm[row0 * 8 + ks * 4 + c] = ssqA;
        ssqm[row1 * 8 + ks * 4 + c] = ssqB;
    }
    __syncthreads();

    if (t < 64) {
        float* dst = g_partial + (size_t)t * NJ * NBLK + blockIdx.x;
#pragma unroll
        for (int j = 0; j < 24; j++)
            dst[(size_t)j * NBLK] = cross[t * 26 + j] + cross[(64 + t) * 26 + j];
        float s = 0.f;
#pragma unroll
        for (int i = 0; i < 8; i++) s += ssqm[t * 8 + i];
        dst[(size_t)24 * NBLK] = s;
    }

    // ===== fused finalize: last block reduces and runs Sinkhorn =====
    __threadfence();
    if (t == 0) s_done = (atomicAdd(&g_count, 1) == NBLK - 1) ? 1u : 0u;
    __syncthreads();
    if (!s_done) return;
    __threadfence();

    float* vsm = &sb[0][0];                  // [64][25]
    __syncthreads();
    for (int task = t; task < BATCH * NJ; task += NTHREADS) {
        int b = task / NJ, j = task % NJ;
        const float4* src = (const float4*)(g_partial + ((size_t)b * NJ + j) * NBLK);
        float4 a = make_float4(0.f, 0.f, 0.f, 0.f);
#pragma unroll 8
        for (int m = 0; m < NBLK / 4; m++) {
            float4 u = src[m];
            a.x += u.x; a.y += u.y; a.z += u.z; a.w += u.w;
        }
        vsm[b * NJ + j] = (a.x + a.y) + (a.z + a.w);
    }
    __syncthreads();

    {
        const int sub = lane & 15;
        const float ap = a_pre[0], ao = a_post[0], ar = a_res[0];
#pragma unroll
        for (int q = 0; q < 4; q++) {
            int b = (w << 3) + (q << 1) + (lane >> 4);
            const float* v = vsm + b * NJ;
            // ms = mean(x^2); eps = FLT_EPSILON (torch RMSNorm eps=None semantics)
            float rinv = rsqrtf(v[24] * (1.0f / (float)D_TOTAL) + 1.1920929e-7f);
            if (sub < 4) {
                float p = ap * (v[sub] * rinv) + b_pre[sub];
                out[b * 4 + sub] = 1.f / (1.f + __expf(-p));
                float qq = ao * (v[4 + sub] * rinv) + b_post[sub];
                out[256 + b * 4 + sub] = 2.f / (1.f + __expf(-qq));
            }
            // Sinkhorn on 4x4: sub = i*4 + j (xor<=8 stays within 16-lane half)
            float rr = ar * (v[8 + sub] * rinv) + b_res[sub];
            float m = rr;
            m = fmaxf(m, __shfl_xor_sync(0xffffffffu, m, 1));
            m = fmaxf(m, __shfl_xor_sync(0xffffffffu, m, 2));
            float M = __expf(rr - m);
#pragma unroll
            for (int itr = 0; itr < 20; itr++) {
                float rs = M + __shfl_xor_sync(0xffffffffu, M, 1);
                rs += __shfl_xor_sync(0xffffffffu, rs, 2);
                M = __fdividef(M, rs + 1e-6f);
                float cs = M + __shfl_xor_sync(0xffffffffu, M, 4);
                cs += __shfl_xor_sync(0xffffffffu, cs, 8);
                M = __fdividef(M, cs + 1e-6f);
            }
            out[512 + b * 16 + sub] = M;
        }
    }
    if (t == 0) g_count = 0;   // reset for next replay
}

extern "C" void kernel_launch(void* const* d_in, const int* in_sizes, int n_in,
                              void* d_out, int out_size)
{
    const float* x     = (const float*)d_in[0];
    const float* wnorm = (const float*)d_in[1];
    const float* Wpre  = (const float*)d_in[2];
    const float* Wpost = (const float*)d_in[3];
    const float* Wres  = (const float*)d_in[4];
    const float* bpre  = (const float*)d_in[5];
    const float* bpost = (const float*)d_in[6];
    const float* bres  = (const float*)d_in[7];
    const float* apre  = (const float*)d_in[8];
    const float* apost = (const float*)d_in[9];
    const float* ares  = (const float*)d_in[10];
    float* out = (float*)d_out;

    mhc_tf32_r9<<<NBLK, NTHREADS>>>(x, wnorm, Wpre, Wpost, Wres,
                                    bpre, bpost, bres, apre, apost, ares, out);
}